// round 4
// baseline (speedup 1.0000x reference)
#include <cuda_runtime.h>
#include <cstdint>

// Problem constants (fixed by the reference)
#define D_MODEL 1024
#define SEQ     2048
#define BATCH   4
#define NH      16
#define DK      64
#define MROWS   (BATCH * SEQ)   // 8192

// Scratch (no allocations allowed)
__device__ float g_Q[(size_t)MROWS * D_MODEL];
__device__ float g_K[(size_t)MROWS * D_MODEL];
__device__ float g_V[(size_t)MROWS * D_MODEL];
__device__ float g_A[(size_t)MROWS * D_MODEL];

__device__ __forceinline__ float f2tf32(float x) {
    uint32_t r;
    asm("cvt.rna.tf32.f32 %0, %1;" : "=r"(r) : "f"(x));
    return __uint_as_float(r);
}
__device__ __forceinline__ uint32_t cvt_u(float x) {
    uint32_t r;
    asm("cvt.rna.tf32.f32 %0, %1;" : "=r"(r) : "f"(x));
    return r;
}
__device__ __forceinline__ float ex2f(float x) {
    float y;
    asm("ex2.approx.ftz.f32 %0, %1;" : "=f"(y) : "f"(x));
    return y;
}

__device__ __forceinline__ void mma_tf32(
    float& c0, float& c1, float& c2, float& c3,
    uint32_t a0, uint32_t a1, uint32_t a2, uint32_t a3,
    uint32_t b0, uint32_t b1)
{
    asm volatile(
        "mma.sync.aligned.m16n8k8.row.col.f32.tf32.tf32.f32 "
        "{%0,%1,%2,%3}, {%4,%5,%6,%7}, {%8,%9}, {%0,%1,%2,%3};"
        : "+f"(c0), "+f"(c1), "+f"(c2), "+f"(c3)
        : "r"(a0), "r"(a1), "r"(a2), "r"(a3), "r"(b0), "r"(b1));
}

#define CP_ASYNC16(dst, src) \
    asm volatile("cp.async.cg.shared.global [%0], [%1], 16;\n" :: "r"(dst), "l"(src))
#define CP_COMMIT() asm volatile("cp.async.commit_group;\n")
#define CP_WAIT2()  asm volatile("cp.async.wait_group 2;\n")

// ---------------------------------------------------------------------------
// TF32 GEMM v2: C[M,N] = A[M,K] @ W[K,N] + bias[N]
// 128x128 block tile, BK=16, 4-stage cp.async pipeline, 8 warps (64x32),
// tf32 RNA conversion on fragment load (ALU pipe), fp32 bits in smem.
// ---------------------------------------------------------------------------
#define STAGES 4
#define GBK 16
#define GAPITCH 20            // banks: 20g+q4 mod 32 -> all distinct
#define GBPITCH 136           // banks: 8q4+g -> all distinct
#define GASTG (128 * GAPITCH) // 2560 floats
#define GBSTG (GBK * GBPITCH) // 2176 floats
#define GEMM_SMEM_BYTES (STAGES * (GASTG + GBSTG) * 4)  // 75776

__global__ __launch_bounds__(256, 2) void gemm_tf32_kernel(
    const float* __restrict__ A, const float* __restrict__ W,
    const float* __restrict__ bias, float* __restrict__ C)
{
    const int N = D_MODEL, K = D_MODEL;
    extern __shared__ float sm[];
    float* As = sm;
    float* Bs = sm + STAGES * GASTG;

    const int tid  = threadIdx.x;
    const int lane = tid & 31;
    const int warp = tid >> 5;
    const int g  = lane >> 2;
    const int q4 = lane & 3;
    const int wm = (warp >> 2) * 64;
    const int wn = (warp & 3) * 32;
    const int rowBase = blockIdx.y * 128;
    const int colBase = blockIdx.x * 128;

    // Loader coordinates
    const int arow = tid >> 2;          // 0..63
    const int acol = (tid & 3) * 4;     // 0..12
    const int brow = tid >> 4;          // 0..15
    const int bcol = (tid & 15) * 4;    // 0..60

    const float* Ag0 = A + (size_t)(rowBase + arow) * K + acol;
    const float* Ag1 = A + (size_t)(rowBase + arow + 64) * K + acol;
    const float* Wg  = W + (size_t)brow * N + colBase + bcol;

    uint32_t aD0[STAGES], aD1[STAGES], bD0[STAGES], bD1[STAGES];
#pragma unroll
    for (int s = 0; s < STAGES; s++) {
        aD0[s] = (uint32_t)__cvta_generic_to_shared(As + s * GASTG + arow * GAPITCH + acol);
        aD1[s] = (uint32_t)__cvta_generic_to_shared(As + s * GASTG + (arow + 64) * GAPITCH + acol);
        bD0[s] = (uint32_t)__cvta_generic_to_shared(Bs + s * GBSTG + brow * GBPITCH + bcol);
        bD1[s] = (uint32_t)__cvta_generic_to_shared(Bs + s * GBSTG + brow * GBPITCH + bcol + 64);
    }

    float acc[4][4][4];
#pragma unroll
    for (int i = 0; i < 4; i++)
#pragma unroll
        for (int j = 0; j < 4; j++)
#pragma unroll
            for (int q = 0; q < 4; q++) acc[i][j][q] = 0.f;

    // Prologue: stages 0..2
#pragma unroll
    for (int s = 0; s < 3; s++) {
        const int k = s * GBK;
        CP_ASYNC16(aD0[s], Ag0 + k);
        CP_ASYNC16(aD1[s], Ag1 + k);
        CP_ASYNC16(bD0[s], Wg + (size_t)k * N);
        CP_ASYNC16(bD1[s], Wg + (size_t)k * N + 64);
        CP_COMMIT();
    }

    int stage = 0;
    for (int k0 = 0; k0 < K; k0 += GBK) {
        CP_WAIT2();
        __syncthreads();

        if (k0 + 3 * GBK < K) {
            const int s = (stage + 3) & 3;
            const int k = k0 + 3 * GBK;
            CP_ASYNC16(aD0[s], Ag0 + k);
            CP_ASYNC16(aD1[s], Ag1 + k);
            CP_ASYNC16(bD0[s], Wg + (size_t)k * N);
            CP_ASYNC16(bD1[s], Wg + (size_t)k * N + 64);
        }
        CP_COMMIT();

        const float* Ac = As + stage * GASTG;
        const float* Bc = Bs + stage * GBSTG;
#pragma unroll
        for (int kk = 0; kk < GBK; kk += 8) {
            uint32_t af[4][4], bf[4][2];
#pragma unroll
            for (int i = 0; i < 4; i++) {
                const int r0 = wm + i * 16 + g;
                const int c  = kk + q4;
                af[i][0] = cvt_u(Ac[r0 * GAPITCH + c]);
                af[i][1] = cvt_u(Ac[(r0 + 8) * GAPITCH + c]);
                af[i][2] = cvt_u(Ac[r0 * GAPITCH + c + 4]);
                af[i][3] = cvt_u(Ac[(r0 + 8) * GAPITCH + c + 4]);
            }
#pragma unroll
            for (int j = 0; j < 4; j++) {
                const int cl = wn + j * 8 + g;
                const int kr = kk + q4;
                bf[j][0] = cvt_u(Bc[kr * GBPITCH + cl]);
                bf[j][1] = cvt_u(Bc[(kr + 4) * GBPITCH + cl]);
            }
#pragma unroll
            for (int i = 0; i < 4; i++)
#pragma unroll
                for (int j = 0; j < 4; j++)
                    mma_tf32(acc[i][j][0], acc[i][j][1], acc[i][j][2], acc[i][j][3],
                             af[i][0], af[i][1], af[i][2], af[i][3],
                             bf[j][0], bf[j][1]);
        }
        stage = (stage + 1) & 3;
    }

    // Epilogue: C = acc + bias
#pragma unroll
    for (int j = 0; j < 4; j++) {
        const int col = colBase + wn + j * 8 + 2 * q4;
        const float b0 = bias[col], b1 = bias[col + 1];
#pragma unroll
        for (int i = 0; i < 4; i++) {
            const int r0 = rowBase + wm + i * 16 + g;
            float2 v0 = make_float2(acc[i][j][0] + b0, acc[i][j][1] + b1);
            float2 v1 = make_float2(acc[i][j][2] + b0, acc[i][j][3] + b1);
            *(float2*)&C[(size_t)r0 * N + col] = v0;
            *(float2*)&C[(size_t)(r0 + 8) * N + col] = v1;
        }
    }
}

// ---------------------------------------------------------------------------
// TF32 tensor-core flash attention (causal). 128 q-rows/CTA, key tiles of 64.
// Q pre-scaled by log2e/8 (softmax in exp2 domain). P kept in registers via
// the k-permutation trick. Longest blocks launch first (qt reversed).
// ---------------------------------------------------------------------------
#define FPITCH 68
#define ATT_SMEM_BYTES ((128 * FPITCH + 2 * 64 * FPITCH) * 4)   // 69632
#define QSCALE 0.1803368801111244f   /* (1/8) * log2(e) */

__global__ __launch_bounds__(256, 2) void attn_tc_kernel(
    const float* __restrict__ Q, const float* __restrict__ K,
    const float* __restrict__ V, float* __restrict__ O)
{
    extern __shared__ float sm[];
    float* sQ = sm;                       // [128][68]
    float* sK = sm + 128 * FPITCH;        // [64][68]
    float* sV = sK + 64 * FPITCH;         // [64][68]

    const int tid  = threadIdx.x;
    const int lane = tid & 31;
    const int warp = tid >> 5;
    const int g  = lane >> 2;
    const int q4 = lane & 3;
    const int qt = gridDim.x - 1 - blockIdx.x;   // longest-first
    const int h  = blockIdx.y;
    const int b  = blockIdx.z;
    const int q0 = qt * 128;
    const size_t base = (size_t)b * SEQ;
    const int hcol = h * DK;

    {
        const int r  = tid >> 4;
        const int c4 = (tid & 15) * 4;
#pragma unroll
        for (int rr = 0; rr < 128; rr += 16) {
            float4 v = *(const float4*)&Q[(base + q0 + rr + r) * D_MODEL + hcol + c4];
            float* d = &sQ[(rr + r) * FPITCH + c4];
            d[0] = f2tf32(v.x * QSCALE); d[1] = f2tf32(v.y * QSCALE);
            d[2] = f2tf32(v.z * QSCALE); d[3] = f2tf32(v.w * QSCALE);
        }
    }
    __syncthreads();

    uint32_t qf[8][4];
    {
        const int r0 = warp * 16 + g;
#pragma unroll
        for (int kk = 0; kk < 8; kk++) {
            const int c = kk * 8 + q4;
            qf[kk][0] = __float_as_uint(sQ[r0 * FPITCH + c]);
            qf[kk][1] = __float_as_uint(sQ[(r0 + 8) * FPITCH + c]);
            qf[kk][2] = __float_as_uint(sQ[r0 * FPITCH + c + 4]);
            qf[kk][3] = __float_as_uint(sQ[(r0 + 8) * FPITCH + c + 4]);
        }
    }

    float oacc[8][4];
#pragma unroll
    for (int j = 0; j < 8; j++)
#pragma unroll
        for (int q = 0; q < 4; q++) oacc[j][q] = 0.f;
    float mrow[2] = {-1e30f, -1e30f};
    float lrow[2] = {0.f, 0.f};

    const int r0g = q0 + warp * 16 + g;
    const int nkt = 2 * qt + 2;

    for (int kt = 0; kt < nkt; kt++) {
        const int k0 = kt * 64;
        __syncthreads();
        {
            const int r  = tid >> 4;
            const int c4 = (tid & 15) * 4;
#pragma unroll
            for (int rr = 0; rr < 64; rr += 16) {
                float4 kv = *(const float4*)&K[(base + k0 + rr + r) * D_MODEL + hcol + c4];
                float* dk = &sK[(rr + r) * FPITCH + c4];
                dk[0] = f2tf32(kv.x); dk[1] = f2tf32(kv.y);
                dk[2] = f2tf32(kv.z); dk[3] = f2tf32(kv.w);
                float4 vv = *(const float4*)&V[(base + k0 + rr + r) * D_MODEL + hcol + c4];
                float* dv = &sV[(rr + r) * FPITCH + c4];
                dv[0] = f2tf32(vv.x); dv[1] = f2tf32(vv.y);
                dv[2] = f2tf32(vv.z); dv[3] = f2tf32(vv.w);
            }
        }
        __syncthreads();

        float sacc[8][4];
#pragma unroll
        for (int j = 0; j < 8; j++)
#pragma unroll
            for (int q = 0; q < 4; q++) sacc[j][q] = 0.f;

#pragma unroll
        for (int kk = 0; kk < 8; kk++) {
#pragma unroll
            for (int j = 0; j < 8; j++) {
                const uint32_t b0 = __float_as_uint(sK[(j * 8 + g) * FPITCH + kk * 8 + q4]);
                const uint32_t b1 = __float_as_uint(sK[(j * 8 + g) * FPITCH + kk * 8 + q4 + 4]);
                mma_tf32(sacc[j][0], sacc[j][1], sacc[j][2], sacc[j][3],
                         qf[kk][0], qf[kk][1], qf[kk][2], qf[kk][3], b0, b1);
            }
        }

        if (kt >= 2 * qt) {
#pragma unroll
            for (int j = 0; j < 8; j++) {
                const int c = k0 + j * 8 + 2 * q4;
                if (c     > r0g)     sacc[j][0] = -1e30f;
                if (c + 1 > r0g)     sacc[j][1] = -1e30f;
                if (c     > r0g + 8) sacc[j][2] = -1e30f;
                if (c + 1 > r0g + 8) sacc[j][3] = -1e30f;
            }
        }

#pragma unroll
        for (int hf = 0; hf < 2; hf++) {
            float mx = -1e30f;
#pragma unroll
            for (int j = 0; j < 8; j++)
                mx = fmaxf(mx, fmaxf(sacc[j][2 * hf], sacc[j][2 * hf + 1]));
            mx = fmaxf(mx, __shfl_xor_sync(0xffffffffu, mx, 1));
            mx = fmaxf(mx, __shfl_xor_sync(0xffffffffu, mx, 2));
            const float mnew = fmaxf(mrow[hf], mx);
            const float aexp = ex2f(mrow[hf] - mnew);
            float rsum = 0.f;
#pragma unroll
            for (int j = 0; j < 8; j++) {
                float p0 = ex2f(sacc[j][2 * hf]     - mnew);
                float p1 = ex2f(sacc[j][2 * hf + 1] - mnew);
                rsum += p0 + p1;
                sacc[j][2 * hf]     = f2tf32(p0);
                sacc[j][2 * hf + 1] = f2tf32(p1);
            }
            rsum += __shfl_xor_sync(0xffffffffu, rsum, 1);
            rsum += __shfl_xor_sync(0xffffffffu, rsum, 2);
            lrow[hf] = lrow[hf] * aexp + rsum;
            mrow[hf] = mnew;
#pragma unroll
            for (int j = 0; j < 8; j++) {
                oacc[j][2 * hf]     *= aexp;
                oacc[j][2 * hf + 1] *= aexp;
            }
        }

#pragma unroll
        for (int kk = 0; kk < 8; kk++) {
            const uint32_t a0 = __float_as_uint(sacc[kk][0]);
            const uint32_t a1 = __float_as_uint(sacc[kk][2]);
            const uint32_t a2 = __float_as_uint(sacc[kk][1]);
            const uint32_t a3 = __float_as_uint(sacc[kk][3]);
#pragma unroll
            for (int j = 0; j < 8; j++) {
                const uint32_t b0 = __float_as_uint(sV[(kk * 8 + 2 * q4)     * FPITCH + j * 8 + g]);
                const uint32_t b1 = __float_as_uint(sV[(kk * 8 + 2 * q4 + 1) * FPITCH + j * 8 + g]);
                mma_tf32(oacc[j][0], oacc[j][1], oacc[j][2], oacc[j][3],
                         a0, a1, a2, a3, b0, b1);
            }
        }
    }

    const float inv0 = 1.f / lrow[0];
    const float inv1 = 1.f / lrow[1];
#pragma unroll
    for (int j = 0; j < 8; j++) {
        const int col = hcol + j * 8 + 2 * q4;
        float2 v0 = make_float2(oacc[j][0] * inv0, oacc[j][1] * inv0);
        float2 v1 = make_float2(oacc[j][2] * inv1, oacc[j][3] * inv1);
        *(float2*)&O[(base + r0g)     * D_MODEL + col] = v0;
        *(float2*)&O[(base + r0g + 8) * D_MODEL + col] = v1;
    }
}

// ---------------------------------------------------------------------------
extern "C" void kernel_launch(void* const* d_in, const int* in_sizes, int n_in,
                              void* d_out, int out_size)
{
    (void)in_sizes; (void)n_in; (void)out_size;
    const float* ctx = (const float*)d_in[0];
    const float* val = (const float*)d_in[1];
    const float* Wq  = (const float*)d_in[3];
    const float* bq  = (const float*)d_in[4];
    const float* Wk  = (const float*)d_in[5];
    const float* bk  = (const float*)d_in[6];
    const float* Wv  = (const float*)d_in[7];
    const float* bv  = (const float*)d_in[8];
    const float* Wo  = (const float*)d_in[9];
    const float* bo  = (const float*)d_in[10];
    float* out = (float*)d_out;

    float *qp, *kp, *vp, *ap;
    cudaGetSymbolAddress((void**)&qp, g_Q);
    cudaGetSymbolAddress((void**)&kp, g_K);
    cudaGetSymbolAddress((void**)&vp, g_V);
    cudaGetSymbolAddress((void**)&ap, g_A);

    cudaFuncSetAttribute(gemm_tf32_kernel,
                         cudaFuncAttributeMaxDynamicSharedMemorySize,
                         GEMM_SMEM_BYTES);
    cudaFuncSetAttribute(attn_tc_kernel,
                         cudaFuncAttributeMaxDynamicSharedMemorySize,
                         ATT_SMEM_BYTES);

    dim3 gblock(256);
    dim3 ggrid(D_MODEL / 128, MROWS / 128);  // (8, 64)

    gemm_tf32_kernel<<<ggrid, gblock, GEMM_SMEM_BYTES>>>(ctx, Wq, bq, qp);
    gemm_tf32_kernel<<<ggrid, gblock, GEMM_SMEM_BYTES>>>(ctx, Wk, bk, kp);
    gemm_tf32_kernel<<<ggrid, gblock, GEMM_SMEM_BYTES>>>(val, Wv, bv, vp);

    dim3 agrid(SEQ / 128, NH, BATCH);  // (16, 16, 4)
    attn_tc_kernel<<<agrid, 256, ATT_SMEM_BYTES>>>(qp, kp, vp, ap);

    gemm_tf32_kernel<<<ggrid, gblock, GEMM_SMEM_BYTES>>>(ap, Wo, bo, out);
}

// round 5
// speedup vs baseline: 1.1246x; 1.1246x over previous
#include <cuda_runtime.h>
#include <cstdint>

// Problem constants (fixed by the reference)
#define D_MODEL 1024
#define SEQ     2048
#define BATCH   4
#define NH      16
#define DK      64
#define MROWS   (BATCH * SEQ)   // 8192

// Scratch (no allocations allowed)
__device__ float g_Q[(size_t)MROWS * D_MODEL];
__device__ float g_K[(size_t)MROWS * D_MODEL];
__device__ float g_V[(size_t)MROWS * D_MODEL];
__device__ float g_A[(size_t)MROWS * D_MODEL];
// tf32-rounded operand copies
__device__ float g_ctx[(size_t)MROWS * D_MODEL];
__device__ float g_val[(size_t)MROWS * D_MODEL];
__device__ float g_Wq[(size_t)D_MODEL * D_MODEL];
__device__ float g_Wk[(size_t)D_MODEL * D_MODEL];
__device__ float g_Wv[(size_t)D_MODEL * D_MODEL];
__device__ float g_Wo[(size_t)D_MODEL * D_MODEL];

__device__ __forceinline__ float f2tf32(float x) {
    uint32_t r;
    asm("cvt.rna.tf32.f32 %0, %1;" : "=r"(r) : "f"(x));
    return __uint_as_float(r);
}
__device__ __forceinline__ float ex2f(float x) {
    float y;
    asm("ex2.approx.ftz.f32 %0, %1;" : "=f"(y) : "f"(x));
    return y;
}

__device__ __forceinline__ void mma_tf32(
    float& c0, float& c1, float& c2, float& c3,
    uint32_t a0, uint32_t a1, uint32_t a2, uint32_t a3,
    uint32_t b0, uint32_t b1)
{
    asm volatile(
        "mma.sync.aligned.m16n8k8.row.col.f32.tf32.tf32.f32 "
        "{%0,%1,%2,%3}, {%4,%5,%6,%7}, {%8,%9}, {%0,%1,%2,%3};"
        : "+f"(c0), "+f"(c1), "+f"(c2), "+f"(c3)
        : "r"(a0), "r"(a1), "r"(a2), "r"(a3), "r"(b0), "r"(b1));
}

#define CP_ASYNC16(dst, src) \
    asm volatile("cp.async.cg.shared.global [%0], [%1], 16;\n" :: "r"(dst), "l"(src))
#define CP_COMMIT() asm volatile("cp.async.commit_group;\n")
#define CP_WAIT2()  asm volatile("cp.async.wait_group 2;\n")

// ---------------------------------------------------------------------------
// Pre-pass: RNA-round fp32 arrays to tf32 (stored as fp32 with zeroed low bits)
// ---------------------------------------------------------------------------
__global__ __launch_bounds__(256) void cvt_kernel(
    const float4* __restrict__ src, float4* __restrict__ dst, int n4)
{
    const int i = blockIdx.x * 256 + threadIdx.x;
    if (i < n4) {
        float4 v = src[i];
        v.x = f2tf32(v.x); v.y = f2tf32(v.y);
        v.z = f2tf32(v.z); v.w = f2tf32(v.w);
        dst[i] = v;
    }
}

// ---------------------------------------------------------------------------
// TF32 GEMM v3 core: C[M,N] = A[M,K] @ W[K,N] + bias[N]
// A and W MUST already be tf32-rounded (raw bits fed to mma).
// 128x128 tile, BK=16, 4-stage cp.async, 8 warps (64x32 warp tiles).
// ---------------------------------------------------------------------------
#define STAGES 4
#define GBK 16
#define GAPITCH 20
#define GBPITCH 136
#define GASTG (128 * GAPITCH)
#define GBSTG (GBK * GBPITCH)
#define GEMM_SMEM_BYTES (STAGES * (GASTG + GBSTG) * 4)  // 75776

__device__ __forceinline__ void gemm_core(
    const float* __restrict__ A, const float* __restrict__ W,
    const float* __restrict__ bias, float* __restrict__ C,
    float* sm, int rowBase, int colBase)
{
    const int N = D_MODEL, K = D_MODEL;
    float* As = sm;
    float* Bs = sm + STAGES * GASTG;

    const int tid  = threadIdx.x;
    const int lane = tid & 31;
    const int warp = tid >> 5;
    const int g  = lane >> 2;
    const int q4 = lane & 3;
    const int wm = (warp >> 2) * 64;
    const int wn = (warp & 3) * 32;

    const int arow = tid >> 2;
    const int acol = (tid & 3) * 4;
    const int brow = tid >> 4;
    const int bcol = (tid & 15) * 4;

    const float* Ag0 = A + (size_t)(rowBase + arow) * K + acol;
    const float* Ag1 = A + (size_t)(rowBase + arow + 64) * K + acol;
    const float* Wg  = W + (size_t)brow * N + colBase + bcol;

    uint32_t aD0[STAGES], aD1[STAGES], bD0[STAGES], bD1[STAGES];
#pragma unroll
    for (int s = 0; s < STAGES; s++) {
        aD0[s] = (uint32_t)__cvta_generic_to_shared(As + s * GASTG + arow * GAPITCH + acol);
        aD1[s] = (uint32_t)__cvta_generic_to_shared(As + s * GASTG + (arow + 64) * GAPITCH + acol);
        bD0[s] = (uint32_t)__cvta_generic_to_shared(Bs + s * GBSTG + brow * GBPITCH + bcol);
        bD1[s] = (uint32_t)__cvta_generic_to_shared(Bs + s * GBSTG + brow * GBPITCH + bcol + 64);
    }

    float acc[4][4][4];
#pragma unroll
    for (int i = 0; i < 4; i++)
#pragma unroll
        for (int j = 0; j < 4; j++)
#pragma unroll
            for (int q = 0; q < 4; q++) acc[i][j][q] = 0.f;

#pragma unroll
    for (int s = 0; s < 3; s++) {
        const int k = s * GBK;
        CP_ASYNC16(aD0[s], Ag0 + k);
        CP_ASYNC16(aD1[s], Ag1 + k);
        CP_ASYNC16(bD0[s], Wg + (size_t)k * N);
        CP_ASYNC16(bD1[s], Wg + (size_t)k * N + 64);
        CP_COMMIT();
    }

    int stage = 0;
    for (int k0 = 0; k0 < K; k0 += GBK) {
        CP_WAIT2();
        __syncthreads();

        if (k0 + 3 * GBK < K) {
            const int s = (stage + 3) & 3;
            const int k = k0 + 3 * GBK;
            CP_ASYNC16(aD0[s], Ag0 + k);
            CP_ASYNC16(aD1[s], Ag1 + k);
            CP_ASYNC16(bD0[s], Wg + (size_t)k * N);
            CP_ASYNC16(bD1[s], Wg + (size_t)k * N + 64);
        }
        CP_COMMIT();

        const uint32_t* Ac = (const uint32_t*)(As + stage * GASTG);
        const uint32_t* Bc = (const uint32_t*)(Bs + stage * GBSTG);
#pragma unroll
        for (int kk = 0; kk < GBK; kk += 8) {
            uint32_t af[4][4], bf[4][2];
#pragma unroll
            for (int i = 0; i < 4; i++) {
                const int r0 = wm + i * 16 + g;
                const int c  = kk + q4;
                af[i][0] = Ac[r0 * GAPITCH + c];
                af[i][1] = Ac[(r0 + 8) * GAPITCH + c];
                af[i][2] = Ac[r0 * GAPITCH + c + 4];
                af[i][3] = Ac[(r0 + 8) * GAPITCH + c + 4];
            }
#pragma unroll
            for (int j = 0; j < 4; j++) {
                const int cl = wn + j * 8 + g;
                const int kr = kk + q4;
                bf[j][0] = Bc[kr * GBPITCH + cl];
                bf[j][1] = Bc[(kr + 4) * GBPITCH + cl];
            }
#pragma unroll
            for (int i = 0; i < 4; i++)
#pragma unroll
                for (int j = 0; j < 4; j++)
                    mma_tf32(acc[i][j][0], acc[i][j][1], acc[i][j][2], acc[i][j][3],
                             af[i][0], af[i][1], af[i][2], af[i][3],
                             bf[j][0], bf[j][1]);
        }
        stage = (stage + 1) & 3;
    }

#pragma unroll
    for (int j = 0; j < 4; j++) {
        const int col = colBase + wn + j * 8 + 2 * q4;
        const float b0 = bias[col], b1 = bias[col + 1];
#pragma unroll
        for (int i = 0; i < 4; i++) {
            const int r0 = rowBase + wm + i * 16 + g;
            float2 v0 = make_float2(acc[i][j][0] + b0, acc[i][j][1] + b1);
            float2 v1 = make_float2(acc[i][j][2] + b0, acc[i][j][3] + b1);
            *(float2*)&C[(size_t)r0 * D_MODEL + col] = v0;
            *(float2*)&C[(size_t)(r0 + 8) * D_MODEL + col] = v1;
        }
    }
}

// Merged Q/K/V projection: blockIdx.z selects (A, W, bias, C)
__global__ __launch_bounds__(256, 2) void gemm_qkv_kernel(
    const float* __restrict__ bq, const float* __restrict__ bk,
    const float* __restrict__ bv)
{
    extern __shared__ float sm[];
    const int z = blockIdx.z;
    const float* A    = (z == 2) ? g_val : g_ctx;
    const float* W    = (z == 0) ? g_Wq : (z == 1) ? g_Wk : g_Wv;
    const float* bias = (z == 0) ? bq   : (z == 1) ? bk   : bv;
    float* C          = (z == 0) ? g_Q  : (z == 1) ? g_K  : g_V;
    gemm_core(A, W, bias, C, sm, blockIdx.y * 128, blockIdx.x * 128);
}

// Single GEMM (output projection)
__global__ __launch_bounds__(256, 2) void gemm_tf32_kernel(
    const float* __restrict__ A, const float* __restrict__ W,
    const float* __restrict__ bias, float* __restrict__ C)
{
    extern __shared__ float sm[];
    gemm_core(A, W, bias, C, sm, blockIdx.y * 128, blockIdx.x * 128);
}

// ---------------------------------------------------------------------------
// TF32 tensor-core flash attention (causal). 128 q-rows/CTA, key tiles of 64.
// Output written tf32-rounded (feeds final GEMM without further conversion).
// ---------------------------------------------------------------------------
#define FPITCH 68
#define ATT_SMEM_BYTES ((128 * FPITCH + 2 * 64 * FPITCH) * 4)   // 69632
#define QSCALE 0.1803368801111244f   /* (1/8) * log2(e) */

__global__ __launch_bounds__(256, 2) void attn_tc_kernel(
    const float* __restrict__ Q, const float* __restrict__ K,
    const float* __restrict__ V, float* __restrict__ O)
{
    extern __shared__ float sm[];
    float* sQ = sm;
    float* sK = sm + 128 * FPITCH;
    float* sV = sK + 64 * FPITCH;

    const int tid  = threadIdx.x;
    const int lane = tid & 31;
    const int warp = tid >> 5;
    const int g  = lane >> 2;
    const int q4 = lane & 3;
    const int qt = gridDim.x - 1 - blockIdx.x;
    const int h  = blockIdx.y;
    const int b  = blockIdx.z;
    const int q0 = qt * 128;
    const size_t base = (size_t)b * SEQ;
    const int hcol = h * DK;

    {
        const int r  = tid >> 4;
        const int c4 = (tid & 15) * 4;
#pragma unroll
        for (int rr = 0; rr < 128; rr += 16) {
            float4 v = *(const float4*)&Q[(base + q0 + rr + r) * D_MODEL + hcol + c4];
            float* d = &sQ[(rr + r) * FPITCH + c4];
            d[0] = f2tf32(v.x * QSCALE); d[1] = f2tf32(v.y * QSCALE);
            d[2] = f2tf32(v.z * QSCALE); d[3] = f2tf32(v.w * QSCALE);
        }
    }
    __syncthreads();

    uint32_t qf[8][4];
    {
        const int r0 = warp * 16 + g;
#pragma unroll
        for (int kk = 0; kk < 8; kk++) {
            const int c = kk * 8 + q4;
            qf[kk][0] = __float_as_uint(sQ[r0 * FPITCH + c]);
            qf[kk][1] = __float_as_uint(sQ[(r0 + 8) * FPITCH + c]);
            qf[kk][2] = __float_as_uint(sQ[r0 * FPITCH + c + 4]);
            qf[kk][3] = __float_as_uint(sQ[(r0 + 8) * FPITCH + c + 4]);
        }
    }

    float oacc[8][4];
#pragma unroll
    for (int j = 0; j < 8; j++)
#pragma unroll
        for (int q = 0; q < 4; q++) oacc[j][q] = 0.f;
    float mrow[2] = {-1e30f, -1e30f};
    float lrow[2] = {0.f, 0.f};

    const int r0g = q0 + warp * 16 + g;
    const int nkt = 2 * qt + 2;

    for (int kt = 0; kt < nkt; kt++) {
        const int k0 = kt * 64;
        __syncthreads();
        {
            const int r  = tid >> 4;
            const int c4 = (tid & 15) * 4;
#pragma unroll
            for (int rr = 0; rr < 64; rr += 16) {
                float4 kv = *(const float4*)&K[(base + k0 + rr + r) * D_MODEL + hcol + c4];
                float* dk = &sK[(rr + r) * FPITCH + c4];
                dk[0] = f2tf32(kv.x); dk[1] = f2tf32(kv.y);
                dk[2] = f2tf32(kv.z); dk[3] = f2tf32(kv.w);
                float4 vv = *(const float4*)&V[(base + k0 + rr + r) * D_MODEL + hcol + c4];
                float* dv = &sV[(rr + r) * FPITCH + c4];
                dv[0] = f2tf32(vv.x); dv[1] = f2tf32(vv.y);
                dv[2] = f2tf32(vv.z); dv[3] = f2tf32(vv.w);
            }
        }
        __syncthreads();

        float sacc[8][4];
#pragma unroll
        for (int j = 0; j < 8; j++)
#pragma unroll
            for (int q = 0; q < 4; q++) sacc[j][q] = 0.f;

#pragma unroll
        for (int kk = 0; kk < 8; kk++) {
#pragma unroll
            for (int j = 0; j < 8; j++) {
                const uint32_t b0 = __float_as_uint(sK[(j * 8 + g) * FPITCH + kk * 8 + q4]);
                const uint32_t b1 = __float_as_uint(sK[(j * 8 + g) * FPITCH + kk * 8 + q4 + 4]);
                mma_tf32(sacc[j][0], sacc[j][1], sacc[j][2], sacc[j][3],
                         qf[kk][0], qf[kk][1], qf[kk][2], qf[kk][3], b0, b1);
            }
        }

        if (kt >= 2 * qt) {
#pragma unroll
            for (int j = 0; j < 8; j++) {
                const int c = k0 + j * 8 + 2 * q4;
                if (c     > r0g)     sacc[j][0] = -1e30f;
                if (c + 1 > r0g)     sacc[j][1] = -1e30f;
                if (c     > r0g + 8) sacc[j][2] = -1e30f;
                if (c + 1 > r0g + 8) sacc[j][3] = -1e30f;
            }
        }

#pragma unroll
        for (int hf = 0; hf < 2; hf++) {
            float mx = -1e30f;
#pragma unroll
            for (int j = 0; j < 8; j++)
                mx = fmaxf(mx, fmaxf(sacc[j][2 * hf], sacc[j][2 * hf + 1]));
            mx = fmaxf(mx, __shfl_xor_sync(0xffffffffu, mx, 1));
            mx = fmaxf(mx, __shfl_xor_sync(0xffffffffu, mx, 2));
            const float mnew = fmaxf(mrow[hf], mx);
            const float aexp = ex2f(mrow[hf] - mnew);
            float rsum = 0.f;
#pragma unroll
            for (int j = 0; j < 8; j++) {
                float p0 = ex2f(sacc[j][2 * hf]     - mnew);
                float p1 = ex2f(sacc[j][2 * hf + 1] - mnew);
                rsum += p0 + p1;
                sacc[j][2 * hf]     = f2tf32(p0);
                sacc[j][2 * hf + 1] = f2tf32(p1);
            }
            rsum += __shfl_xor_sync(0xffffffffu, rsum, 1);
            rsum += __shfl_xor_sync(0xffffffffu, rsum, 2);
            lrow[hf] = lrow[hf] * aexp + rsum;
            mrow[hf] = mnew;
#pragma unroll
            for (int j = 0; j < 8; j++) {
                oacc[j][2 * hf]     *= aexp;
                oacc[j][2 * hf + 1] *= aexp;
            }
        }

#pragma unroll
        for (int kk = 0; kk < 8; kk++) {
            const uint32_t a0 = __float_as_uint(sacc[kk][0]);
            const uint32_t a1 = __float_as_uint(sacc[kk][2]);
            const uint32_t a2 = __float_as_uint(sacc[kk][1]);
            const uint32_t a3 = __float_as_uint(sacc[kk][3]);
#pragma unroll
            for (int j = 0; j < 8; j++) {
                const uint32_t b0 = __float_as_uint(sV[(kk * 8 + 2 * q4)     * FPITCH + j * 8 + g]);
                const uint32_t b1 = __float_as_uint(sV[(kk * 8 + 2 * q4 + 1) * FPITCH + j * 8 + g]);
                mma_tf32(oacc[j][0], oacc[j][1], oacc[j][2], oacc[j][3],
                         a0, a1, a2, a3, b0, b1);
            }
        }
    }

    // Normalize + store, tf32-rounded (final GEMM feeds raw bits to mma)
    const float inv0 = 1.f / lrow[0];
    const float inv1 = 1.f / lrow[1];
#pragma unroll
    for (int j = 0; j < 8; j++) {
        const int col = hcol + j * 8 + 2 * q4;
        float2 v0 = make_float2(f2tf32(oacc[j][0] * inv0), f2tf32(oacc[j][1] * inv0));
        float2 v1 = make_float2(f2tf32(oacc[j][2] * inv1), f2tf32(oacc[j][3] * inv1));
        *(float2*)&O[(base + r0g)     * D_MODEL + col] = v0;
        *(float2*)&O[(base + r0g + 8) * D_MODEL + col] = v1;
    }
}

// ---------------------------------------------------------------------------
extern "C" void kernel_launch(void* const* d_in, const int* in_sizes, int n_in,
                              void* d_out, int out_size)
{
    (void)in_sizes; (void)n_in; (void)out_size;
    const float* ctx = (const float*)d_in[0];
    const float* val = (const float*)d_in[1];
    const float* Wq  = (const float*)d_in[3];
    const float* bq  = (const float*)d_in[4];
    const float* Wk  = (const float*)d_in[5];
    const float* bk  = (const float*)d_in[6];
    const float* Wv  = (const float*)d_in[7];
    const float* bv  = (const float*)d_in[8];
    const float* Wo  = (const float*)d_in[9];
    const float* bo  = (const float*)d_in[10];
    float* out = (float*)d_out;

    float *qp, *kp, *vp, *ap, *ctxp, *valp, *wqp, *wkp, *wvp, *wop;
    cudaGetSymbolAddress((void**)&qp,   g_Q);
    cudaGetSymbolAddress((void**)&kp,   g_K);
    cudaGetSymbolAddress((void**)&vp,   g_V);
    cudaGetSymbolAddress((void**)&ap,   g_A);
    cudaGetSymbolAddress((void**)&ctxp, g_ctx);
    cudaGetSymbolAddress((void**)&valp, g_val);
    cudaGetSymbolAddress((void**)&wqp,  g_Wq);
    cudaGetSymbolAddress((void**)&wkp,  g_Wk);
    cudaGetSymbolAddress((void**)&wvp,  g_Wv);
    cudaGetSymbolAddress((void**)&wop,  g_Wo);

    cudaFuncSetAttribute(gemm_qkv_kernel,
                         cudaFuncAttributeMaxDynamicSharedMemorySize, GEMM_SMEM_BYTES);
    cudaFuncSetAttribute(gemm_tf32_kernel,
                         cudaFuncAttributeMaxDynamicSharedMemorySize, GEMM_SMEM_BYTES);
    cudaFuncSetAttribute(attn_tc_kernel,
                         cudaFuncAttributeMaxDynamicSharedMemorySize, ATT_SMEM_BYTES);

    // Pre-pass: tf32-round all GEMM operands
    const int nAct = MROWS * D_MODEL / 4;      // 2M float4
    const int nW   = D_MODEL * D_MODEL / 4;    // 256K float4
    cvt_kernel<<<(nAct + 255) / 256, 256>>>((const float4*)ctx, (float4*)ctxp, nAct);
    cvt_kernel<<<(nAct + 255) / 256, 256>>>((const float4*)val, (float4*)valp, nAct);
    cvt_kernel<<<(nW + 255) / 256, 256>>>((const float4*)Wq, (float4*)wqp, nW);
    cvt_kernel<<<(nW + 255) / 256, 256>>>((const float4*)Wk, (float4*)wkp, nW);
    cvt_kernel<<<(nW + 255) / 256, 256>>>((const float4*)Wv, (float4*)wvp, nW);
    cvt_kernel<<<(nW + 255) / 256, 256>>>((const float4*)Wo, (float4*)wop, nW);

    // Merged Q/K/V projection
    dim3 qkvGrid(D_MODEL / 128, MROWS / 128, 3);  // (8, 64, 3)
    gemm_qkv_kernel<<<qkvGrid, 256, GEMM_SMEM_BYTES>>>(bq, bk, bv);

    // Attention
    dim3 agrid(SEQ / 128, NH, BATCH);  // (16, 16, 4)
    attn_tc_kernel<<<agrid, 256, ATT_SMEM_BYTES>>>(qp, kp, vp, ap);

    // Output projection
    dim3 ggrid(D_MODEL / 128, MROWS / 128);  // (8, 64)
    gemm_tf32_kernel<<<ggrid, 256, GEMM_SMEM_BYTES>>>(ap, wop, bo, out);
}

// round 6
// speedup vs baseline: 1.1335x; 1.0078x over previous
#include <cuda_runtime.h>
#include <cstdint>

// Problem constants (fixed by the reference)
#define D_MODEL 1024
#define SEQ     2048
#define BATCH   4
#define NH      16
#define DK      64
#define MROWS   (BATCH * SEQ)   // 8192

// Scratch (no allocations allowed)
__device__ float g_Q[(size_t)MROWS * D_MODEL];
__device__ float g_K[(size_t)MROWS * D_MODEL];
__device__ float g_V[(size_t)MROWS * D_MODEL];
__device__ float g_A[(size_t)MROWS * D_MODEL];
// tf32-rounded operand copies
__device__ float g_ctx[(size_t)MROWS * D_MODEL];
__device__ float g_val[(size_t)MROWS * D_MODEL];
__device__ float g_Wq[(size_t)D_MODEL * D_MODEL];
__device__ float g_Wk[(size_t)D_MODEL * D_MODEL];
__device__ float g_Wv[(size_t)D_MODEL * D_MODEL];
__device__ float g_Wo[(size_t)D_MODEL * D_MODEL];

__device__ __forceinline__ float f2tf32(float x) {
    uint32_t r;
    asm("cvt.rna.tf32.f32 %0, %1;" : "=r"(r) : "f"(x));
    return __uint_as_float(r);
}
__device__ __forceinline__ float ex2f(float x) {
    float y;
    asm("ex2.approx.ftz.f32 %0, %1;" : "=f"(y) : "f"(x));
    return y;
}

__device__ __forceinline__ void mma_tf32(
    float& c0, float& c1, float& c2, float& c3,
    uint32_t a0, uint32_t a1, uint32_t a2, uint32_t a3,
    uint32_t b0, uint32_t b1)
{
    asm volatile(
        "mma.sync.aligned.m16n8k8.row.col.f32.tf32.tf32.f32 "
        "{%0,%1,%2,%3}, {%4,%5,%6,%7}, {%8,%9}, {%0,%1,%2,%3};"
        : "+f"(c0), "+f"(c1), "+f"(c2), "+f"(c3)
        : "r"(a0), "r"(a1), "r"(a2), "r"(a3), "r"(b0), "r"(b1));
}

#define CP_ASYNC16(dst, src) \
    asm volatile("cp.async.cg.shared.global [%0], [%1], 16;\n" :: "r"(dst), "l"(src))
#define CP_COMMIT() asm volatile("cp.async.commit_group;\n")
#define CP_WAIT2()  asm volatile("cp.async.wait_group 2;\n")

// ---------------------------------------------------------------------------
// Pre-pass v2: RNA-round fp32 -> tf32 bits, 4x float4 per thread per iter
// (MLP=4 hides DRAM latency), grid-stride.
// ---------------------------------------------------------------------------
__global__ __launch_bounds__(256) void cvt_act_kernel(
    const float4* __restrict__ src, float4* __restrict__ dst, int n4)
{
    const int stride = gridDim.x * 256;
    int i = blockIdx.x * 256 + threadIdx.x;
    for (; i + 3 * stride < n4; i += 4 * stride) {
        float4 v0 = src[i];
        float4 v1 = src[i + stride];
        float4 v2 = src[i + 2 * stride];
        float4 v3 = src[i + 3 * stride];
        v0.x = f2tf32(v0.x); v0.y = f2tf32(v0.y); v0.z = f2tf32(v0.z); v0.w = f2tf32(v0.w);
        v1.x = f2tf32(v1.x); v1.y = f2tf32(v1.y); v1.z = f2tf32(v1.z); v1.w = f2tf32(v1.w);
        v2.x = f2tf32(v2.x); v2.y = f2tf32(v2.y); v2.z = f2tf32(v2.z); v2.w = f2tf32(v2.w);
        v3.x = f2tf32(v3.x); v3.y = f2tf32(v3.y); v3.z = f2tf32(v3.z); v3.w = f2tf32(v3.w);
        dst[i] = v0;
        dst[i + stride] = v1;
        dst[i + 2 * stride] = v2;
        dst[i + 3 * stride] = v3;
    }
    for (; i < n4; i += stride) {
        float4 v = src[i];
        v.x = f2tf32(v.x); v.y = f2tf32(v.y); v.z = f2tf32(v.z); v.w = f2tf32(v.w);
        dst[i] = v;
    }
}

// All 4 weight matrices in one launch; blockIdx.z selects the array.
__global__ __launch_bounds__(256) void cvt_w_kernel(
    const float4* __restrict__ wq, const float4* __restrict__ wk,
    const float4* __restrict__ wv, const float4* __restrict__ wo)
{
    const int n4 = D_MODEL * D_MODEL / 4;
    const int z = blockIdx.z;
    const float4* src = (z == 0) ? wq : (z == 1) ? wk : (z == 2) ? wv : wo;
    float4* dst = (z == 0) ? (float4*)g_Wq : (z == 1) ? (float4*)g_Wk
                : (z == 2) ? (float4*)g_Wv : (float4*)g_Wo;
    const int stride = gridDim.x * 256;
    int i = blockIdx.x * 256 + threadIdx.x;
    for (; i + 3 * stride < n4; i += 4 * stride) {
        float4 v0 = src[i];
        float4 v1 = src[i + stride];
        float4 v2 = src[i + 2 * stride];
        float4 v3 = src[i + 3 * stride];
        v0.x = f2tf32(v0.x); v0.y = f2tf32(v0.y); v0.z = f2tf32(v0.z); v0.w = f2tf32(v0.w);
        v1.x = f2tf32(v1.x); v1.y = f2tf32(v1.y); v1.z = f2tf32(v1.z); v1.w = f2tf32(v1.w);
        v2.x = f2tf32(v2.x); v2.y = f2tf32(v2.y); v2.z = f2tf32(v2.z); v2.w = f2tf32(v2.w);
        v3.x = f2tf32(v3.x); v3.y = f2tf32(v3.y); v3.z = f2tf32(v3.z); v3.w = f2tf32(v3.w);
        dst[i] = v0;
        dst[i + stride] = v1;
        dst[i + 2 * stride] = v2;
        dst[i + 3 * stride] = v3;
    }
    for (; i < n4; i += stride) {
        float4 v = src[i];
        v.x = f2tf32(v.x); v.y = f2tf32(v.y); v.z = f2tf32(v.z); v.w = f2tf32(v.w);
        dst[i] = v;
    }
}

// ---------------------------------------------------------------------------
// TF32 GEMM v3 core: C[M,N] = A[M,K] @ W[K,N] + bias[N]
// A and W MUST already be tf32-rounded (raw bits fed to mma).
// 128x128 tile, BK=16, 4-stage cp.async, 8 warps (64x32 warp tiles).
// ---------------------------------------------------------------------------
#define STAGES 4
#define GBK 16
#define GAPITCH 20
#define GBPITCH 136
#define GASTG (128 * GAPITCH)
#define GBSTG (GBK * GBPITCH)
#define GEMM_SMEM_BYTES (STAGES * (GASTG + GBSTG) * 4)  // 75776

__device__ __forceinline__ void gemm_core(
    const float* __restrict__ A, const float* __restrict__ W,
    const float* __restrict__ bias, float* __restrict__ C,
    float* sm, int rowBase, int colBase)
{
    const int N = D_MODEL, K = D_MODEL;
    float* As = sm;
    float* Bs = sm + STAGES * GASTG;

    const int tid  = threadIdx.x;
    const int lane = tid & 31;
    const int warp = tid >> 5;
    const int g  = lane >> 2;
    const int q4 = lane & 3;
    const int wm = (warp >> 2) * 64;
    const int wn = (warp & 3) * 32;

    const int arow = tid >> 2;
    const int acol = (tid & 3) * 4;
    const int brow = tid >> 4;
    const int bcol = (tid & 15) * 4;

    const float* Ag0 = A + (size_t)(rowBase + arow) * K + acol;
    const float* Ag1 = A + (size_t)(rowBase + arow + 64) * K + acol;
    const float* Wg  = W + (size_t)brow * N + colBase + bcol;

    uint32_t aD0[STAGES], aD1[STAGES], bD0[STAGES], bD1[STAGES];
#pragma unroll
    for (int s = 0; s < STAGES; s++) {
        aD0[s] = (uint32_t)__cvta_generic_to_shared(As + s * GASTG + arow * GAPITCH + acol);
        aD1[s] = (uint32_t)__cvta_generic_to_shared(As + s * GASTG + (arow + 64) * GAPITCH + acol);
        bD0[s] = (uint32_t)__cvta_generic_to_shared(Bs + s * GBSTG + brow * GBPITCH + bcol);
        bD1[s] = (uint32_t)__cvta_generic_to_shared(Bs + s * GBSTG + brow * GBPITCH + bcol + 64);
    }

    float acc[4][4][4];
#pragma unroll
    for (int i = 0; i < 4; i++)
#pragma unroll
        for (int j = 0; j < 4; j++)
#pragma unroll
            for (int q = 0; q < 4; q++) acc[i][j][q] = 0.f;

#pragma unroll
    for (int s = 0; s < 3; s++) {
        const int k = s * GBK;
        CP_ASYNC16(aD0[s], Ag0 + k);
        CP_ASYNC16(aD1[s], Ag1 + k);
        CP_ASYNC16(bD0[s], Wg + (size_t)k * N);
        CP_ASYNC16(bD1[s], Wg + (size_t)k * N + 64);
        CP_COMMIT();
    }

    int stage = 0;
    for (int k0 = 0; k0 < K; k0 += GBK) {
        CP_WAIT2();
        __syncthreads();

        if (k0 + 3 * GBK < K) {
            const int s = (stage + 3) & 3;
            const int k = k0 + 3 * GBK;
            CP_ASYNC16(aD0[s], Ag0 + k);
            CP_ASYNC16(aD1[s], Ag1 + k);
            CP_ASYNC16(bD0[s], Wg + (size_t)k * N);
            CP_ASYNC16(bD1[s], Wg + (size_t)k * N + 64);
        }
        CP_COMMIT();

        const uint32_t* Ac = (const uint32_t*)(As + stage * GASTG);
        const uint32_t* Bc = (const uint32_t*)(Bs + stage * GBSTG);
#pragma unroll
        for (int kk = 0; kk < GBK; kk += 8) {
            uint32_t af[4][4], bf[4][2];
#pragma unroll
            for (int i = 0; i < 4; i++) {
                const int r0 = wm + i * 16 + g;
                const int c  = kk + q4;
                af[i][0] = Ac[r0 * GAPITCH + c];
                af[i][1] = Ac[(r0 + 8) * GAPITCH + c];
                af[i][2] = Ac[r0 * GAPITCH + c + 4];
                af[i][3] = Ac[(r0 + 8) * GAPITCH + c + 4];
            }
#pragma unroll
            for (int j = 0; j < 4; j++) {
                const int cl = wn + j * 8 + g;
                const int kr = kk + q4;
                bf[j][0] = Bc[kr * GBPITCH + cl];
                bf[j][1] = Bc[(kr + 4) * GBPITCH + cl];
            }
#pragma unroll
            for (int i = 0; i < 4; i++)
#pragma unroll
                for (int j = 0; j < 4; j++)
                    mma_tf32(acc[i][j][0], acc[i][j][1], acc[i][j][2], acc[i][j][3],
                             af[i][0], af[i][1], af[i][2], af[i][3],
                             bf[j][0], bf[j][1]);
        }
        stage = (stage + 1) & 3;
    }

#pragma unroll
    for (int j = 0; j < 4; j++) {
        const int col = colBase + wn + j * 8 + 2 * q4;
        const float b0 = bias[col], b1 = bias[col + 1];
#pragma unroll
        for (int i = 0; i < 4; i++) {
            const int r0 = rowBase + wm + i * 16 + g;
            float2 v0 = make_float2(acc[i][j][0] + b0, acc[i][j][1] + b1);
            float2 v1 = make_float2(acc[i][j][2] + b0, acc[i][j][3] + b1);
            *(float2*)&C[(size_t)r0 * D_MODEL + col] = v0;
            *(float2*)&C[(size_t)(r0 + 8) * D_MODEL + col] = v1;
        }
    }
}

// Merged Q/K/V projection: blockIdx.z selects (A, W, bias, C)
__global__ __launch_bounds__(256, 2) void gemm_qkv_kernel(
    const float* __restrict__ bq, const float* __restrict__ bk,
    const float* __restrict__ bv)
{
    extern __shared__ float sm[];
    const int z = blockIdx.z;
    const float* A    = (z == 2) ? g_val : g_ctx;
    const float* W    = (z == 0) ? g_Wq : (z == 1) ? g_Wk : g_Wv;
    const float* bias = (z == 0) ? bq   : (z == 1) ? bk   : bv;
    float* C          = (z == 0) ? g_Q  : (z == 1) ? g_K  : g_V;
    gemm_core(A, W, bias, C, sm, blockIdx.y * 128, blockIdx.x * 128);
}

// Single GEMM (output projection)
__global__ __launch_bounds__(256, 2) void gemm_tf32_kernel(
    const float* __restrict__ A, const float* __restrict__ W,
    const float* __restrict__ bias, float* __restrict__ C)
{
    extern __shared__ float sm[];
    gemm_core(A, W, bias, C, sm, blockIdx.y * 128, blockIdx.x * 128);
}

// ---------------------------------------------------------------------------
// TF32 tensor-core flash attention (causal). 128 q-rows/CTA, key tiles of 64.
// Output written tf32-rounded (feeds final GEMM without further conversion).
// ---------------------------------------------------------------------------
#define FPITCH 68
#define ATT_SMEM_BYTES ((128 * FPITCH + 2 * 64 * FPITCH) * 4)   // 69632
#define QSCALE 0.1803368801111244f   /* (1/8) * log2(e) */

__global__ __launch_bounds__(256, 2) void attn_tc_kernel(
    const float* __restrict__ Q, const float* __restrict__ K,
    const float* __restrict__ V, float* __restrict__ O)
{
    extern __shared__ float sm[];
    float* sQ = sm;
    float* sK = sm + 128 * FPITCH;
    float* sV = sK + 64 * FPITCH;

    const int tid  = threadIdx.x;
    const int lane = tid & 31;
    const int warp = tid >> 5;
    const int g  = lane >> 2;
    const int q4 = lane & 3;
    const int qt = gridDim.x - 1 - blockIdx.x;
    const int h  = blockIdx.y;
    const int b  = blockIdx.z;
    const int q0 = qt * 128;
    const size_t base = (size_t)b * SEQ;
    const int hcol = h * DK;

    {
        const int r  = tid >> 4;
        const int c4 = (tid & 15) * 4;
#pragma unroll
        for (int rr = 0; rr < 128; rr += 16) {
            float4 v = *(const float4*)&Q[(base + q0 + rr + r) * D_MODEL + hcol + c4];
            float* d = &sQ[(rr + r) * FPITCH + c4];
            d[0] = f2tf32(v.x * QSCALE); d[1] = f2tf32(v.y * QSCALE);
            d[2] = f2tf32(v.z * QSCALE); d[3] = f2tf32(v.w * QSCALE);
        }
    }
    __syncthreads();

    uint32_t qf[8][4];
    {
        const int r0 = warp * 16 + g;
#pragma unroll
        for (int kk = 0; kk < 8; kk++) {
            const int c = kk * 8 + q4;
            qf[kk][0] = __float_as_uint(sQ[r0 * FPITCH + c]);
            qf[kk][1] = __float_as_uint(sQ[(r0 + 8) * FPITCH + c]);
            qf[kk][2] = __float_as_uint(sQ[r0 * FPITCH + c + 4]);
            qf[kk][3] = __float_as_uint(sQ[(r0 + 8) * FPITCH + c + 4]);
        }
    }

    float oacc[8][4];
#pragma unroll
    for (int j = 0; j < 8; j++)
#pragma unroll
        for (int q = 0; q < 4; q++) oacc[j][q] = 0.f;
    float mrow[2] = {-1e30f, -1e30f};
    float lrow[2] = {0.f, 0.f};

    const int r0g = q0 + warp * 16 + g;
    const int nkt = 2 * qt + 2;

    for (int kt = 0; kt < nkt; kt++) {
        const int k0 = kt * 64;
        __syncthreads();
        {
            const int r  = tid >> 4;
            const int c4 = (tid & 15) * 4;
#pragma unroll
            for (int rr = 0; rr < 64; rr += 16) {
                float4 kv = *(const float4*)&K[(base + k0 + rr + r) * D_MODEL + hcol + c4];
                float* dk = &sK[(rr + r) * FPITCH + c4];
                dk[0] = f2tf32(kv.x); dk[1] = f2tf32(kv.y);
                dk[2] = f2tf32(kv.z); dk[3] = f2tf32(kv.w);
                float4 vv = *(const float4*)&V[(base + k0 + rr + r) * D_MODEL + hcol + c4];
                float* dv = &sV[(rr + r) * FPITCH + c4];
                dv[0] = f2tf32(vv.x); dv[1] = f2tf32(vv.y);
                dv[2] = f2tf32(vv.z); dv[3] = f2tf32(vv.w);
            }
        }
        __syncthreads();

        float sacc[8][4];
#pragma unroll
        for (int j = 0; j < 8; j++)
#pragma unroll
            for (int q = 0; q < 4; q++) sacc[j][q] = 0.f;

#pragma unroll
        for (int kk = 0; kk < 8; kk++) {
#pragma unroll
            for (int j = 0; j < 8; j++) {
                const uint32_t b0 = __float_as_uint(sK[(j * 8 + g) * FPITCH + kk * 8 + q4]);
                const uint32_t b1 = __float_as_uint(sK[(j * 8 + g) * FPITCH + kk * 8 + q4 + 4]);
                mma_tf32(sacc[j][0], sacc[j][1], sacc[j][2], sacc[j][3],
                         qf[kk][0], qf[kk][1], qf[kk][2], qf[kk][3], b0, b1);
            }
        }

        if (kt >= 2 * qt) {
#pragma unroll
            for (int j = 0; j < 8; j++) {
                const int c = k0 + j * 8 + 2 * q4;
                if (c     > r0g)     sacc[j][0] = -1e30f;
                if (c + 1 > r0g)     sacc[j][1] = -1e30f;
                if (c     > r0g + 8) sacc[j][2] = -1e30f;
                if (c + 1 > r0g + 8) sacc[j][3] = -1e30f;
            }
        }

#pragma unroll
        for (int hf = 0; hf < 2; hf++) {
            float mx = -1e30f;
#pragma unroll
            for (int j = 0; j < 8; j++)
                mx = fmaxf(mx, fmaxf(sacc[j][2 * hf], sacc[j][2 * hf + 1]));
            mx = fmaxf(mx, __shfl_xor_sync(0xffffffffu, mx, 1));
            mx = fmaxf(mx, __shfl_xor_sync(0xffffffffu, mx, 2));
            const float mnew = fmaxf(mrow[hf], mx);
            const float aexp = ex2f(mrow[hf] - mnew);
            float rsum = 0.f;
#pragma unroll
            for (int j = 0; j < 8; j++) {
                float p0 = ex2f(sacc[j][2 * hf]     - mnew);
                float p1 = ex2f(sacc[j][2 * hf + 1] - mnew);
                rsum += p0 + p1;
                sacc[j][2 * hf]     = f2tf32(p0);
                sacc[j][2 * hf + 1] = f2tf32(p1);
            }
            rsum += __shfl_xor_sync(0xffffffffu, rsum, 1);
            rsum += __shfl_xor_sync(0xffffffffu, rsum, 2);
            lrow[hf] = lrow[hf] * aexp + rsum;
            mrow[hf] = mnew;
#pragma unroll
            for (int j = 0; j < 8; j++) {
                oacc[j][2 * hf]     *= aexp;
                oacc[j][2 * hf + 1] *= aexp;
            }
        }

#pragma unroll
        for (int kk = 0; kk < 8; kk++) {
            const uint32_t a0 = __float_as_uint(sacc[kk][0]);
            const uint32_t a1 = __float_as_uint(sacc[kk][2]);
            const uint32_t a2 = __float_as_uint(sacc[kk][1]);
            const uint32_t a3 = __float_as_uint(sacc[kk][3]);
#pragma unroll
            for (int j = 0; j < 8; j++) {
                const uint32_t b0 = __float_as_uint(sV[(kk * 8 + 2 * q4)     * FPITCH + j * 8 + g]);
                const uint32_t b1 = __float_as_uint(sV[(kk * 8 + 2 * q4 + 1) * FPITCH + j * 8 + g]);
                mma_tf32(oacc[j][0], oacc[j][1], oacc[j][2], oacc[j][3],
                         a0, a1, a2, a3, b0, b1);
            }
        }
    }

    const float inv0 = 1.f / lrow[0];
    const float inv1 = 1.f / lrow[1];
#pragma unroll
    for (int j = 0; j < 8; j++) {
        const int col = hcol + j * 8 + 2 * q4;
        float2 v0 = make_float2(f2tf32(oacc[j][0] * inv0), f2tf32(oacc[j][1] * inv0));
        float2 v1 = make_float2(f2tf32(oacc[j][2] * inv1), f2tf32(oacc[j][3] * inv1));
        *(float2*)&O[(base + r0g)     * D_MODEL + col] = v0;
        *(float2*)&O[(base + r0g + 8) * D_MODEL + col] = v1;
    }
}

// ---------------------------------------------------------------------------
extern "C" void kernel_launch(void* const* d_in, const int* in_sizes, int n_in,
                              void* d_out, int out_size)
{
    (void)in_sizes; (void)n_in; (void)out_size;
    const float* ctx = (const float*)d_in[0];
    const float* val = (const float*)d_in[1];
    const float* Wq  = (const float*)d_in[3];
    const float* bq  = (const float*)d_in[4];
    const float* Wk  = (const float*)d_in[5];
    const float* bk  = (const float*)d_in[6];
    const float* Wv  = (const float*)d_in[7];
    const float* bv  = (const float*)d_in[8];
    const float* Wo  = (const float*)d_in[9];
    const float* bo  = (const float*)d_in[10];
    float* out = (float*)d_out;

    float *qp, *kp, *vp, *ap, *ctxp, *valp, *wop;
    cudaGetSymbolAddress((void**)&qp,   g_Q);
    cudaGetSymbolAddress((void**)&kp,   g_K);
    cudaGetSymbolAddress((void**)&vp,   g_V);
    cudaGetSymbolAddress((void**)&ap,   g_A);
    cudaGetSymbolAddress((void**)&ctxp, g_ctx);
    cudaGetSymbolAddress((void**)&valp, g_val);
    cudaGetSymbolAddress((void**)&wop,  g_Wo);

    cudaFuncSetAttribute(gemm_qkv_kernel,
                         cudaFuncAttributeMaxDynamicSharedMemorySize, GEMM_SMEM_BYTES);
    cudaFuncSetAttribute(gemm_tf32_kernel,
                         cudaFuncAttributeMaxDynamicSharedMemorySize, GEMM_SMEM_BYTES);
    cudaFuncSetAttribute(attn_tc_kernel,
                         cudaFuncAttributeMaxDynamicSharedMemorySize, ATT_SMEM_BYTES);

    // Pre-pass: tf32-round all GEMM operands (high-MLP grid-stride)
    const int nAct = MROWS * D_MODEL / 4;      // 2M float4
    cvt_act_kernel<<<2048, 256>>>((const float4*)ctx, (float4*)ctxp, nAct);
    cvt_act_kernel<<<2048, 256>>>((const float4*)val, (float4*)valp, nAct);
    dim3 wgrid(256, 1, 4);                     // 4 weight arrays, one launch
    cvt_w_kernel<<<wgrid, 256>>>((const float4*)Wq, (const float4*)Wk,
                                 (const float4*)Wv, (const float4*)Wo);

    // Merged Q/K/V projection
    dim3 qkvGrid(D_MODEL / 128, MROWS / 128, 3);  // (8, 64, 3)
    gemm_qkv_kernel<<<qkvGrid, 256, GEMM_SMEM_BYTES>>>(bq, bk, bv);

    // Attention
    dim3 agrid(SEQ / 128, NH, BATCH);  // (16, 16, 4)
    attn_tc_kernel<<<agrid, 256, ATT_SMEM_BYTES>>>(qp, kp, vp, ap);

    // Output projection
    dim3 ggrid(D_MODEL / 128, MROWS / 128);  // (8, 64)
    gemm_tf32_kernel<<<ggrid, 256, GEMM_SMEM_BYTES>>>(ap, wop, bo, out);
}